// round 14
// baseline (speedup 1.0000x reference)
#include <cuda_runtime.h>
#include <cuda_bf16.h>
#include <math.h>

// Problem constants
#define BB 32
#define LL 1024
#define XX 1024
#define YY 1024
#define AA 16
#define MM 48          // 16 action rows + 32 batch rows
#define MSPLIT 4
#define MH (MM / MSPLIT)   // 12 m-rows per split
#define XC 2               // x columns per thread in k1
#define YT 64          // number of Y tiles in stage 1
#define YS (YY / YT)   // 16 y-rows per tile
#define RPB 8          // rows per block in k4 (1 row per warp)
#define BPB (LL / RPB) // 128 blocks per batch in k4

// Scratch (allocation-free: __device__ globals)
__device__ float g_part[YT][MM][XX];   // partial GEMM sums, 12 MB
__device__ float g_wy[BB][XX];         // Wy[b,x]
__device__ float g_pm[BB][BPB];        // per-block partial max
__device__ float g_ps[BB][BPB];        // per-block partial sumexp
__device__ int   g_cnt[BB];            // arrival counters (reset by last block)

#define GDC_LAUNCH() asm volatile("griddepcontrol.launch_dependents;" ::: "memory")
#define GDC_WAIT()   asm volatile("griddepcontrol.wait;" ::: "memory")

__device__ __forceinline__ void lse_combine(float& m, float& s, float m2, float s2) {
    const float M = fmaxf(m, m2);
    s = s * __expf(m - M) + s2 * __expf(m2 - M);
    m = M;
}

// ---------------------------------------------------------------------------
// K1: partial skinny GEMM. g_part[yt][m][x] = sum_{y in tile} in[m,y]*W[y,x]
// grid (XX/256, YT, MSPLIT=4), block 128. Thread owns TWO x columns
// (x, x+128) and MH=12 m-rows -> 24 accumulators. (Measured best: 9.5us.)
// ---------------------------------------------------------------------------
__global__ __launch_bounds__(128) void k1_partial_gemm(
    const float* __restrict__ wa_h,   // [A, Y]
    const float* __restrict__ y_in,   // [B, Y]
    const float* __restrict__ weight) // [Y, X]
{
    GDC_LAUNCH();   // let k3/k4 start early; they gate via gdc.wait
    __shared__ float in_s[YS * MH];   // transposed: [yl][m], 768 B
    const int x  = blockIdx.x * (128 * XC) + threadIdx.x;   // col0; col1 = x+128
    const int y0 = blockIdx.y * YS;
    const int m0 = blockIdx.z * MH;

    for (int i = threadIdx.x; i < YS * MH; i += 128) {
        const int yl = i / MH;
        const int m  = m0 + i % MH;
        float v;
        if (m < AA) v = wa_h[m * YY + (y0 + yl)];
        else        v = y_in[(m - AA) * YY + (y0 + yl)];
        in_s[i] = v;
    }
    __syncthreads();

    float acc0[MH], acc1[MH];
#pragma unroll
    for (int m = 0; m < MH; m++) { acc0[m] = 0.0f; acc1[m] = 0.0f; }

#pragma unroll 8
    for (int yl = 0; yl < YS; yl++) {
        const float* wr = weight + (size_t)(y0 + yl) * XX + x;
        const float w0 = wr[0];
        const float w1 = wr[128];
        const float4* r = reinterpret_cast<const float4*>(&in_s[yl * MH]);
#pragma unroll
        for (int q = 0; q < MH / 4; q++) {
            const float4 v = r[q];
            acc0[4 * q + 0] = fmaf(w0, v.x, acc0[4 * q + 0]);
            acc0[4 * q + 1] = fmaf(w0, v.y, acc0[4 * q + 1]);
            acc0[4 * q + 2] = fmaf(w0, v.z, acc0[4 * q + 2]);
            acc0[4 * q + 3] = fmaf(w0, v.w, acc0[4 * q + 3]);
            acc1[4 * q + 0] = fmaf(w1, v.x, acc1[4 * q + 0]);
            acc1[4 * q + 1] = fmaf(w1, v.y, acc1[4 * q + 1]);
            acc1[4 * q + 2] = fmaf(w1, v.z, acc1[4 * q + 2]);
            acc1[4 * q + 3] = fmaf(w1, v.w, acc1[4 * q + 3]);
        }
    }

#pragma unroll
    for (int m = 0; m < MH; m++) {
        g_part[blockIdx.y][m0 + m][x]       = acc0[m];
        g_part[blockIdx.y][m0 + m][x + 128] = acc1[m];
    }
}

// ---------------------------------------------------------------------------
// Block reductions for 256-thread blocks (8 warps)
// ---------------------------------------------------------------------------
__device__ __forceinline__ float brmax256(float v, float* red) {
    const int tid = threadIdx.x;
#pragma unroll
    for (int o = 16; o; o >>= 1) v = fmaxf(v, __shfl_xor_sync(0xffffffffu, v, o));
    if ((tid & 31) == 0) red[tid >> 5] = v;
    __syncthreads();
    if (tid < 8) {
        v = red[tid];
#pragma unroll
        for (int o = 4; o; o >>= 1) v = fmaxf(v, __shfl_xor_sync(0xffu, v, o));
        if (tid == 0) red[0] = v;
    }
    __syncthreads();
    v = red[0];
    __syncthreads();
    return v;
}

__device__ __forceinline__ float brsum256(float v, float* red) {
    const int tid = threadIdx.x;
#pragma unroll
    for (int o = 16; o; o >>= 1) v += __shfl_xor_sync(0xffffffffu, v, o);
    if ((tid & 31) == 0) red[tid >> 5] = v;
    __syncthreads();
    if (tid < 8) {
        v = red[tid];
#pragma unroll
        for (int o = 4; o; o >>= 1) v += __shfl_xor_sync(0xffu, v, o);
        if (tid == 0) red[0] = v;
    }
    __syncthreads();
    v = red[0];
    __syncthreads();
    return v;
}

// ---------------------------------------------------------------------------
// K3: per-batch softmax(score row) + Wy[b,x] = yW[b,x]*score2[x] + bias[x]
// grid 32, block 256, float4: thread t owns x columns 4t..4t+3.
// LDG.128 doubles per-SM bandwidth on the g_part reduction vs scalar loads.
// PDL: launches during k1, waits before reading g_part.
// ---------------------------------------------------------------------------
__global__ __launch_bounds__(256) void k3_softmax_wy(
    const int* __restrict__ actions,
    const float* __restrict__ bias)
{
    GDC_LAUNCH();           // let k4 start early
    __shared__ float red[8];
    const int b = blockIdx.x;
    const int t = threadIdx.x;   // float4 column index

    GDC_WAIT();             // wait for k1 grid completion (acquire g_part)
    const int act = actions[b];

    const float4* pa = reinterpret_cast<const float4*>(&g_part[0][act][0])    + t;
    const float4* py = reinterpret_cast<const float4*>(&g_part[0][AA + b][0]) + t;
    const int stride4 = (MM * XX) / 4;   // float4 stride between yt tiles

    float4 sa = make_float4(0.f, 0.f, 0.f, 0.f);
    float4 sy = make_float4(0.f, 0.f, 0.f, 0.f);
#pragma unroll 8
    for (int yt = 0; yt < YT; yt++) {
        const float4 a = pa[yt * stride4];
        const float4 y = py[yt * stride4];
        sa.x += a.x; sa.y += a.y; sa.z += a.z; sa.w += a.w;
        sy.x += y.x; sy.y += y.y; sy.z += y.z; sy.w += y.w;
    }

    const float lmax = fmaxf(fmaxf(sa.x, sa.y), fmaxf(sa.z, sa.w));
    const float mx   = brmax256(lmax, red);

    float4 e;
    e.x = __expf(sa.x - mx); e.y = __expf(sa.y - mx);
    e.z = __expf(sa.z - mx); e.w = __expf(sa.w - mx);
    const float lsum = (e.x + e.y) + (e.z + e.w);
    const float sum  = brsum256(lsum, red);
    const float inv  = 1.0f / sum;

    const float4 bi = reinterpret_cast<const float4*>(bias)[t];
    float4 wy;
    wy.x = sy.x * (e.x * inv) + bi.x;
    wy.y = sy.y * (e.y * inv) + bi.y;
    wy.z = sy.z * (e.z * inv) + bi.z;
    wy.w = sy.w * (e.w * inv) + bi.w;
    reinterpret_cast<float4*>(&g_wy[b][0])[t] = wy;
}

// ---------------------------------------------------------------------------
// K4 fused: z[b,l] = dot(x[b,l,:], Wy[b,:]) (mask -> -inf), written straight
// to out; per-batch log_softmax finished in-place by the last-arriving block.
// grid (B, BPB=128), block 256: 8 warps x 1 row (measured-best shape).
// PDL: blocks prefetch their x rows BEFORE gdc.wait.
// Release fence executed by tid0 only (cumulative fence after barrier).
// ---------------------------------------------------------------------------
__global__ __launch_bounds__(256) void k4_fused(
    const float* __restrict__ x,
    const unsigned char* __restrict__ x_mask,
    float* __restrict__ out)
{
    __shared__ float4 wy_s[XX / 4];
    __shared__ float  zrow[RPB];
    __shared__ float  s_elect;
    __shared__ float  s_lse;
    const int b     = blockIdx.x;
    const int chunk = blockIdx.y;
    const int tid   = threadIdx.x;
    const int warp  = tid >> 5;
    const int lane  = tid & 31;

    const int l = chunk * RPB + warp;
    const float4* xr =
        reinterpret_cast<const float4*>(x + ((size_t)b * LL + l) * XX);

    // 1) issue x loads (independent of upstream kernels) — overlaps k1/k3
    float4 xv[8];
#pragma unroll
    for (int it = 0; it < 8; it++) xv[it] = xr[it * 32 + lane];
    const unsigned char mk = (lane == 0) ? x_mask[b * LL + l] : 0;

    // 2) wait for k3 grid (acquire g_wy), then stage Wy
    GDC_WAIT();
    for (int i = tid; i < XX / 4; i += 256)
        wy_s[i] = reinterpret_cast<const float4*>(&g_wy[b][0])[i];
    __syncthreads();

    // 3) compute
    float acc = 0.0f;
#pragma unroll
    for (int it = 0; it < 8; it++) {
        const float4 wv = wy_s[it * 32 + lane];
        acc = fmaf(xv[it].x, wv.x, acc);
        acc = fmaf(xv[it].y, wv.y, acc);
        acc = fmaf(xv[it].z, wv.z, acc);
        acc = fmaf(xv[it].w, wv.w, acc);
    }
#pragma unroll
    for (int o = 16; o; o >>= 1) acc += __shfl_xor_sync(0xffffffffu, acc, o);
    if (lane == 0)
        zrow[warp] = mk ? -INFINITY : acc;
    __syncthreads();

    // write z chunk directly to out + block partial (m, s)
    if (tid < RPB)
        out[b * LL + chunk * RPB + tid] = zrow[tid];
    if (warp == 0 && lane < RPB) {
        float m = zrow[lane];
        float s = 1.0f;
#pragma unroll
        for (int o = 4; o; o >>= 1) {
            float m2 = __shfl_xor_sync(0xffu, m, o);
            float s2 = __shfl_xor_sync(0xffu, s, o);
            lse_combine(m, s, m2, s2);
        }
        if (lane == 0) {
            g_pm[b][chunk] = m;
            g_ps[b][chunk] = s;
        }
    }
    __syncthreads();   // block writes ordered before tid0's fence (cumulative)

    // release: single-thread fence + arrival (threadFenceReduction pattern)
    if (tid == 0) {
        __threadfence();
        const int old = atomicAdd(&g_cnt[b], 1);
        s_elect = (old == BPB - 1) ? 1.0f : 0.0f;
    }
    __syncthreads();
    if (s_elect == 0.0f) return;

    // ---- last block for batch b: finish log_softmax in-place ----
    __threadfence();                 // acquire all producers' writes
    if (tid == 0) g_cnt[b] = 0;      // reset for next graph replay

    if (warp == 0) {
        // combine BPB=128 partials: each lane owns 4
        float m = g_pm[b][lane];
        float s = g_ps[b][lane];
#pragma unroll
        for (int k = 1; k < 4; k++)
            lse_combine(m, s, g_pm[b][lane + 32 * k], g_ps[b][lane + 32 * k]);
#pragma unroll
        for (int o = 16; o; o >>= 1) {
            float m2 = __shfl_xor_sync(0xffffffffu, m, o);
            float s2 = __shfl_xor_sync(0xffffffffu, s, o);
            lse_combine(m, s, m2, s2);
        }
        if (lane == 0) s_lse = m + logf(s);
    }
    __syncthreads();
    const float lse = s_lse;

    float4* po = reinterpret_cast<float4*>(out + b * LL);
    for (int i = tid; i < LL / 4; i += 256) {
        float4 z = po[i];
        po[i] = make_float4(z.x - lse, z.y - lse, z.z - lse, z.w - lse);
    }
}

// ---------------------------------------------------------------------------
// Launch. Input order: x, y, x_mask, actions, weight, bias, wa_h
// PDL chain k1 -> k3 -> k4: prologues overlap upstream kernels.
// ---------------------------------------------------------------------------
extern "C" void kernel_launch(void* const* d_in, const int* in_sizes, int n_in,
                              void* d_out, int out_size)
{
    const float*         x       = (const float*)d_in[0];
    const float*         y_in    = (const float*)d_in[1];
    const unsigned char* x_mask  = (const unsigned char*)d_in[2];
    const int*           actions = (const int*)d_in[3];
    const float*         weight  = (const float*)d_in[4];
    const float*         bias    = (const float*)d_in[5];
    const float*         wa_h    = (const float*)d_in[6];
    float*               out     = (float*)d_out;

    k1_partial_gemm<<<dim3(XX / (128 * XC), YT, MSPLIT), 128>>>(wa_h, y_in, weight);

    cudaLaunchAttribute pdl[1];
    pdl[0].id = cudaLaunchAttributeProgrammaticStreamSerialization;
    pdl[0].val.programmaticStreamSerializationAllowed = 1;

    {
        cudaLaunchConfig_t cfg = {};
        cfg.gridDim  = dim3(BB);
        cfg.blockDim = dim3(256);
        cfg.attrs    = pdl;
        cfg.numAttrs = 1;
        cudaLaunchKernelEx(&cfg, k3_softmax_wy, actions, bias);
    }
    {
        cudaLaunchConfig_t cfg = {};
        cfg.gridDim  = dim3(BB, BPB);
        cfg.blockDim = dim3(256);
        cfg.attrs    = pdl;
        cfg.numAttrs = 1;
        cudaLaunchKernelEx(&cfg, k4_fused, x, x_mask, out);
    }
}

// round 15
// speedup vs baseline: 1.1941x; 1.1941x over previous
#include <cuda_runtime.h>
#include <cuda_bf16.h>
#include <math.h>

// Problem constants
#define BB 32
#define LL 1024
#define XX 1024
#define YY 1024
#define AA 16
#define MM 48          // 16 action rows + 32 batch rows
#define MSPLIT 4
#define MH (MM / MSPLIT)   // 12 m-rows per split
#define XC 2               // x columns per thread in k1
#define YT 64          // number of Y tiles in stage 1
#define YS (YY / YT)   // 16 y-rows per tile
#define RPB 8          // rows per block in k4 (1 row per warp)
#define BPB (LL / RPB) // 128 blocks per batch in k4

// Scratch (allocation-free: __device__ globals)
__device__ float g_part[YT][MM][XX];   // partial GEMM sums, 12 MB
__device__ float g_wy[BB][XX];         // Wy[b,x]
__device__ float g_pm[BB][BPB];        // per-block partial max
__device__ float g_ps[BB][BPB];        // per-block partial sumexp
__device__ int   g_cnt[BB];            // arrival counters (reset by last block)

#define GDC_LAUNCH() asm volatile("griddepcontrol.launch_dependents;" ::: "memory")
#define GDC_WAIT()   asm volatile("griddepcontrol.wait;" ::: "memory")

__device__ __forceinline__ void lse_combine(float& m, float& s, float m2, float s2) {
    const float M = fmaxf(m, m2);
    s = s * __expf(m - M) + s2 * __expf(m2 - M);
    m = M;
}

// ---------------------------------------------------------------------------
// K1: partial skinny GEMM. g_part[yt][m][x] = sum_{y in tile} in[m,y]*W[y,x]
// grid (XX/256, YT, MSPLIT=4), block 128. Thread owns TWO x columns
// (x, x+128) and MH=12 m-rows -> 24 accumulators. (Measured best: 9.5us.)
// ---------------------------------------------------------------------------
__global__ __launch_bounds__(128) void k1_partial_gemm(
    const float* __restrict__ wa_h,   // [A, Y]
    const float* __restrict__ y_in,   // [B, Y]
    const float* __restrict__ weight) // [Y, X]
{
    GDC_LAUNCH();   // let k3/k4 start early; they gate via gdc.wait
    __shared__ float in_s[YS * MH];   // transposed: [yl][m], 768 B
    const int x  = blockIdx.x * (128 * XC) + threadIdx.x;   // col0; col1 = x+128
    const int y0 = blockIdx.y * YS;
    const int m0 = blockIdx.z * MH;

    for (int i = threadIdx.x; i < YS * MH; i += 128) {
        const int yl = i / MH;
        const int m  = m0 + i % MH;
        float v;
        if (m < AA) v = wa_h[m * YY + (y0 + yl)];
        else        v = y_in[(m - AA) * YY + (y0 + yl)];
        in_s[i] = v;
    }
    __syncthreads();

    float acc0[MH], acc1[MH];
#pragma unroll
    for (int m = 0; m < MH; m++) { acc0[m] = 0.0f; acc1[m] = 0.0f; }

#pragma unroll 8
    for (int yl = 0; yl < YS; yl++) {
        const float* wr = weight + (size_t)(y0 + yl) * XX + x;
        const float w0 = wr[0];
        const float w1 = wr[128];
        const float4* r = reinterpret_cast<const float4*>(&in_s[yl * MH]);
#pragma unroll
        for (int q = 0; q < MH / 4; q++) {
            const float4 v = r[q];
            acc0[4 * q + 0] = fmaf(w0, v.x, acc0[4 * q + 0]);
            acc0[4 * q + 1] = fmaf(w0, v.y, acc0[4 * q + 1]);
            acc0[4 * q + 2] = fmaf(w0, v.z, acc0[4 * q + 2]);
            acc0[4 * q + 3] = fmaf(w0, v.w, acc0[4 * q + 3]);
            acc1[4 * q + 0] = fmaf(w1, v.x, acc1[4 * q + 0]);
            acc1[4 * q + 1] = fmaf(w1, v.y, acc1[4 * q + 1]);
            acc1[4 * q + 2] = fmaf(w1, v.z, acc1[4 * q + 2]);
            acc1[4 * q + 3] = fmaf(w1, v.w, acc1[4 * q + 3]);
        }
    }

#pragma unroll
    for (int m = 0; m < MH; m++) {
        g_part[blockIdx.y][m0 + m][x]       = acc0[m];
        g_part[blockIdx.y][m0 + m][x + 128] = acc1[m];
    }
}

// ---------------------------------------------------------------------------
// Block reductions for 1024-thread blocks (32 warps)
// ---------------------------------------------------------------------------
__device__ __forceinline__ float brmax1024(float v, float* red) {
    const int tid = threadIdx.x;
#pragma unroll
    for (int o = 16; o; o >>= 1) v = fmaxf(v, __shfl_xor_sync(0xffffffffu, v, o));
    if ((tid & 31) == 0) red[tid >> 5] = v;
    __syncthreads();
    if (tid < 32) {
        v = red[tid];
#pragma unroll
        for (int o = 16; o; o >>= 1) v = fmaxf(v, __shfl_xor_sync(0xffffffffu, v, o));
        if (tid == 0) red[0] = v;
    }
    __syncthreads();
    v = red[0];
    __syncthreads();
    return v;
}

__device__ __forceinline__ float brsum1024(float v, float* red) {
    const int tid = threadIdx.x;
#pragma unroll
    for (int o = 16; o; o >>= 1) v += __shfl_xor_sync(0xffffffffu, v, o);
    if ((tid & 31) == 0) red[tid >> 5] = v;
    __syncthreads();
    if (tid < 32) {
        v = red[tid];
#pragma unroll
        for (int o = 16; o; o >>= 1) v += __shfl_xor_sync(0xffffffffu, v, o);
        if (tid == 0) red[0] = v;
    }
    __syncthreads();
    v = red[0];
    __syncthreads();
    return v;
}

// ---------------------------------------------------------------------------
// K3: per-batch softmax(score row) + Wy[b,x] = yW[b,x]*score2[x] + bias[x]
// grid 32, block 1024, scalar loads: 32 warps/SM hide the L2-hit latency on
// the g_part reduction (measured better than the 256-thread float4 variant).
// PDL: launches during k1, waits before reading g_part.
// ---------------------------------------------------------------------------
__global__ __launch_bounds__(1024) void k3_softmax_wy(
    const int* __restrict__ actions,
    const float* __restrict__ bias)
{
    GDC_LAUNCH();           // let k4 start early
    __shared__ float red[32];
    const int b = blockIdx.x;
    const int x = threadIdx.x;

    GDC_WAIT();             // wait for k1 grid completion (acquire g_part)
    const int act = actions[b];

    float sa = 0.0f, sy = 0.0f;
#pragma unroll
    for (int yt = 0; yt < YT; yt++) {
        sa += g_part[yt][act][x];
        sy += g_part[yt][AA + b][x];
    }

    const float mx  = brmax1024(sa, red);
    const float e   = expf(sa - mx);
    const float sum = brsum1024(e, red);

    g_wy[b][x] = sy * (e / sum) + bias[x];
}

// ---------------------------------------------------------------------------
// K4 fused: z[b,l] = dot(x[b,l,:], Wy[b,:]) (mask -> -inf), written straight
// to out; per-batch log_softmax finished in-place by the last-arriving block.
// grid (B, BPB=128), block 256: 8 warps x 1 row (measured-best shape).
// x loads use __ldcs (evict-first): x is streamed once (128 MB) and must not
// evict the reused lines (g_wy, g_pm/g_ps, out) from L2.
// PDL: blocks prefetch their x rows BEFORE gdc.wait.
// ---------------------------------------------------------------------------
__global__ __launch_bounds__(256) void k4_fused(
    const float* __restrict__ x,
    const unsigned char* __restrict__ x_mask,
    float* __restrict__ out)
{
    __shared__ float4 wy_s[XX / 4];
    __shared__ float  zrow[RPB];
    __shared__ float  s_elect;
    __shared__ float  s_lse;
    const int b     = blockIdx.x;
    const int chunk = blockIdx.y;
    const int tid   = threadIdx.x;
    const int warp  = tid >> 5;
    const int lane  = tid & 31;

    const int l = chunk * RPB + warp;
    const float4* xr =
        reinterpret_cast<const float4*>(x + ((size_t)b * LL + l) * XX);

    // 1) issue x loads (independent of upstream kernels) — overlaps k1/k3
    float4 xv[8];
#pragma unroll
    for (int it = 0; it < 8; it++) xv[it] = __ldcs(&xr[it * 32 + lane]);
    const unsigned char mk = (lane == 0) ? x_mask[b * LL + l] : 0;

    // 2) wait for k3 grid (acquire g_wy), then stage Wy
    GDC_WAIT();
    for (int i = tid; i < XX / 4; i += 256)
        wy_s[i] = reinterpret_cast<const float4*>(&g_wy[b][0])[i];
    __syncthreads();

    // 3) compute
    float acc = 0.0f;
#pragma unroll
    for (int it = 0; it < 8; it++) {
        const float4 wv = wy_s[it * 32 + lane];
        acc = fmaf(xv[it].x, wv.x, acc);
        acc = fmaf(xv[it].y, wv.y, acc);
        acc = fmaf(xv[it].z, wv.z, acc);
        acc = fmaf(xv[it].w, wv.w, acc);
    }
#pragma unroll
    for (int o = 16; o; o >>= 1) acc += __shfl_xor_sync(0xffffffffu, acc, o);
    if (lane == 0)
        zrow[warp] = mk ? -INFINITY : acc;
    __syncthreads();

    // write z chunk directly to out + block partial (m, s)
    if (tid < RPB)
        out[b * LL + chunk * RPB + tid] = zrow[tid];
    if (warp == 0 && lane < RPB) {
        float m = zrow[lane];
        float s = 1.0f;
#pragma unroll
        for (int o = 4; o; o >>= 1) {
            float m2 = __shfl_xor_sync(0xffu, m, o);
            float s2 = __shfl_xor_sync(0xffu, s, o);
            lse_combine(m, s, m2, s2);
        }
        if (lane == 0) {
            g_pm[b][chunk] = m;
            g_ps[b][chunk] = s;
        }
    }
    __threadfence();
    __syncthreads();

    if (tid == 0) {
        const int old = atomicAdd(&g_cnt[b], 1);
        s_elect = (old == BPB - 1) ? 1.0f : 0.0f;
    }
    __syncthreads();
    if (s_elect == 0.0f) return;

    // ---- last block for batch b: finish log_softmax in-place ----
    __threadfence();                 // acquire all producers' writes
    if (tid == 0) g_cnt[b] = 0;      // reset for next graph replay

    if (warp == 0) {
        // combine BPB=128 partials: each lane owns 4
        float m = g_pm[b][lane];
        float s = g_ps[b][lane];
#pragma unroll
        for (int k = 1; k < 4; k++)
            lse_combine(m, s, g_pm[b][lane + 32 * k], g_ps[b][lane + 32 * k]);
#pragma unroll
        for (int o = 16; o; o >>= 1) {
            float m2 = __shfl_xor_sync(0xffffffffu, m, o);
            float s2 = __shfl_xor_sync(0xffffffffu, s, o);
            lse_combine(m, s, m2, s2);
        }
        if (lane == 0) s_lse = m + logf(s);
    }
    __syncthreads();
    const float lse = s_lse;

    float4* po = reinterpret_cast<float4*>(out + b * LL);
    for (int i = tid; i < LL / 4; i += 256) {
        float4 z = po[i];
        po[i] = make_float4(z.x - lse, z.y - lse, z.z - lse, z.w - lse);
    }
}

// ---------------------------------------------------------------------------
// Launch. Input order: x, y, x_mask, actions, weight, bias, wa_h
// PDL chain k1 -> k3 -> k4: prologues overlap upstream kernels.
// ---------------------------------------------------------------------------
extern "C" void kernel_launch(void* const* d_in, const int* in_sizes, int n_in,
                              void* d_out, int out_size)
{
    const float*         x       = (const float*)d_in[0];
    const float*         y_in    = (const float*)d_in[1];
    const unsigned char* x_mask  = (const unsigned char*)d_in[2];
    const int*           actions = (const int*)d_in[3];
    const float*         weight  = (const float*)d_in[4];
    const float*         bias    = (const float*)d_in[5];
    const float*         wa_h    = (const float*)d_in[6];
    float*               out     = (float*)d_out;

    k1_partial_gemm<<<dim3(XX / (128 * XC), YT, MSPLIT), 128>>>(wa_h, y_in, weight);

    cudaLaunchAttribute pdl[1];
    pdl[0].id = cudaLaunchAttributeProgrammaticStreamSerialization;
    pdl[0].val.programmaticStreamSerializationAllowed = 1;

    {
        cudaLaunchConfig_t cfg = {};
        cfg.gridDim  = dim3(BB);
        cfg.blockDim = dim3(1024);
        cfg.attrs    = pdl;
        cfg.numAttrs = 1;
        cudaLaunchKernelEx(&cfg, k3_softmax_wy, actions, bias);
    }
    {
        cudaLaunchConfig_t cfg = {};
        cfg.gridDim  = dim3(BB, BPB);
        cfg.blockDim = dim3(256);
        cfg.attrs    = pdl;
        cfg.numAttrs = 1;
        cudaLaunchKernelEx(&cfg, k4_fused, x, x_mask, out);
    }
}

// round 17
// speedup vs baseline: 1.1994x; 1.0044x over previous
#include <cuda_runtime.h>
#include <cuda_bf16.h>
#include <math.h>

// Problem constants
#define BB 32
#define LL 1024
#define XX 1024
#define YY 1024
#define AA 16
#define MM 48          // 16 action rows + 32 batch rows
#define MSPLIT 4
#define MH (MM / MSPLIT)   // 12 m-rows per split
#define XC 2               // x columns per thread in k1
#define YT 64          // number of Y tiles in stage 1
#define YS (YY / YT)   // 16 y-rows per tile
#define RPB 8          // rows per block in k4 (1 row per warp)
#define BPB (LL / RPB) // 128 blocks per batch in k4

// Scratch (allocation-free: __device__ globals)
__device__ float g_part[YT][MM][XX];   // partial GEMM sums, 12 MB
__device__ float g_wy[BB][XX];         // Wy[b,x]
__device__ float g_pm[BB][BPB];        // per-block partial max
__device__ float g_ps[BB][BPB];        // per-block partial sumexp
__device__ int   g_cnt[BB];            // arrival counters (reset by last block)

#define GDC_LAUNCH() asm volatile("griddepcontrol.launch_dependents;" ::: "memory")
#define GDC_WAIT()   asm volatile("griddepcontrol.wait;" ::: "memory")

__device__ __forceinline__ void lse_combine(float& m, float& s, float m2, float s2) {
    const float M = fmaxf(m, m2);
    s = s * __expf(m - M) + s2 * __expf(m2 - M);
    m = M;
}

// ---------------------------------------------------------------------------
// K1: partial skinny GEMM. g_part[yt][m][x] = sum_{y in tile} in[m,y]*W[y,x]
// grid (XX/256, YT, MSPLIT=4), block 128. Thread owns TWO x columns
// (x, x+128) and MH=12 m-rows -> 24 accumulators. (Measured best: 9.5us.)
// ---------------------------------------------------------------------------
__global__ __launch_bounds__(128) void k1_partial_gemm(
    const float* __restrict__ wa_h,   // [A, Y]
    const float* __restrict__ y_in,   // [B, Y]
    const float* __restrict__ weight) // [Y, X]
{
    GDC_LAUNCH();   // let k3/k4 start early; they gate via gdc.wait
    __shared__ float in_s[YS * MH];   // transposed: [yl][m], 768 B
    const int x  = blockIdx.x * (128 * XC) + threadIdx.x;   // col0; col1 = x+128
    const int y0 = blockIdx.y * YS;
    const int m0 = blockIdx.z * MH;

    for (int i = threadIdx.x; i < YS * MH; i += 128) {
        const int yl = i / MH;
        const int m  = m0 + i % MH;
        float v;
        if (m < AA) v = wa_h[m * YY + (y0 + yl)];
        else        v = y_in[(m - AA) * YY + (y0 + yl)];
        in_s[i] = v;
    }
    __syncthreads();

    float acc0[MH], acc1[MH];
#pragma unroll
    for (int m = 0; m < MH; m++) { acc0[m] = 0.0f; acc1[m] = 0.0f; }

#pragma unroll 8
    for (int yl = 0; yl < YS; yl++) {
        const float* wr = weight + (size_t)(y0 + yl) * XX + x;
        const float w0 = wr[0];
        const float w1 = wr[128];
        const float4* r = reinterpret_cast<const float4*>(&in_s[yl * MH]);
#pragma unroll
        for (int q = 0; q < MH / 4; q++) {
            const float4 v = r[q];
            acc0[4 * q + 0] = fmaf(w0, v.x, acc0[4 * q + 0]);
            acc0[4 * q + 1] = fmaf(w0, v.y, acc0[4 * q + 1]);
            acc0[4 * q + 2] = fmaf(w0, v.z, acc0[4 * q + 2]);
            acc0[4 * q + 3] = fmaf(w0, v.w, acc0[4 * q + 3]);
            acc1[4 * q + 0] = fmaf(w1, v.x, acc1[4 * q + 0]);
            acc1[4 * q + 1] = fmaf(w1, v.y, acc1[4 * q + 1]);
            acc1[4 * q + 2] = fmaf(w1, v.z, acc1[4 * q + 2]);
            acc1[4 * q + 3] = fmaf(w1, v.w, acc1[4 * q + 3]);
        }
    }

#pragma unroll
    for (int m = 0; m < MH; m++) {
        g_part[blockIdx.y][m0 + m][x]       = acc0[m];
        g_part[blockIdx.y][m0 + m][x + 128] = acc1[m];
    }
}

// ---------------------------------------------------------------------------
// Block reductions for 1024-thread blocks (32 warps)
// ---------------------------------------------------------------------------
__device__ __forceinline__ float brmax1024(float v, float* red) {
    const int tid = threadIdx.x;
#pragma unroll
    for (int o = 16; o; o >>= 1) v = fmaxf(v, __shfl_xor_sync(0xffffffffu, v, o));
    if ((tid & 31) == 0) red[tid >> 5] = v;
    __syncthreads();
    if (tid < 32) {
        v = red[tid];
#pragma unroll
        for (int o = 16; o; o >>= 1) v = fmaxf(v, __shfl_xor_sync(0xffffffffu, v, o));
        if (tid == 0) red[0] = v;
    }
    __syncthreads();
    v = red[0];
    __syncthreads();
    return v;
}

__device__ __forceinline__ float brsum1024(float v, float* red) {
    const int tid = threadIdx.x;
#pragma unroll
    for (int o = 16; o; o >>= 1) v += __shfl_xor_sync(0xffffffffu, v, o);
    if ((tid & 31) == 0) red[tid >> 5] = v;
    __syncthreads();
    if (tid < 32) {
        v = red[tid];
#pragma unroll
        for (int o = 16; o; o >>= 1) v += __shfl_xor_sync(0xffffffffu, v, o);
        if (tid == 0) red[0] = v;
    }
    __syncthreads();
    v = red[0];
    __syncthreads();
    return v;
}

// ---------------------------------------------------------------------------
// K3: per-batch softmax(score row) + Wy[b,x] = yW[b,x]*score2[x] + bias[x]
// grid 32, block 1024, scalar loads: 32 warps/SM hide the L2-hit latency on
// the g_part reduction.
// PDL: launches during k1, waits before reading g_part.
// ---------------------------------------------------------------------------
__global__ __launch_bounds__(1024) void k3_softmax_wy(
    const int* __restrict__ actions,
    const float* __restrict__ bias)
{
    GDC_LAUNCH();           // let k4 start early
    __shared__ float red[32];
    const int b = blockIdx.x;
    const int x = threadIdx.x;

    GDC_WAIT();             // wait for k1 grid completion (acquire g_part)
    const int act = actions[b];

    float sa = 0.0f, sy = 0.0f;
#pragma unroll
    for (int yt = 0; yt < YT; yt++) {
        sa += g_part[yt][act][x];
        sy += g_part[yt][AA + b][x];
    }

    const float mx  = brmax1024(sa, red);
    const float e   = expf(sa - mx);
    const float sum = brsum1024(e, red);

    g_wy[b][x] = sy * (e / sum) + bias[x];
}

// ---------------------------------------------------------------------------
// K4 fused: z[b,l] = dot(x[b,l,:], Wy[b,:]) (mask -> -inf), written straight
// to out; per-batch log_softmax finished in-place by the last-arriving block.
// grid (B, BPB=128), block 256: 8 warps x 1 row (measured-best shape).
// x loads use __ldcs (evict-first streaming). Wy is read per warp with PLAIN
// COHERENT loads (NOT __ldg — the .nc path returned stale data under PDL
// concurrency with k3 in R16): no smem staging, no block-wide barrier between
// the x prefetch and the dot product.
// PDL: blocks prefetch their x rows BEFORE gdc.wait.
// ---------------------------------------------------------------------------
__global__ __launch_bounds__(256) void k4_fused(
    const float* __restrict__ x,
    const unsigned char* __restrict__ x_mask,
    float* __restrict__ out)
{
    __shared__ float  zrow[RPB];
    __shared__ float  s_elect;
    __shared__ float  s_lse;
    const int b     = blockIdx.x;
    const int chunk = blockIdx.y;
    const int tid   = threadIdx.x;
    const int warp  = tid >> 5;
    const int lane  = tid & 31;

    const int l = chunk * RPB + warp;
    const float4* xr =
        reinterpret_cast<const float4*>(x + ((size_t)b * LL + l) * XX);

    // 1) issue x loads (independent of upstream kernels) — overlaps k1/k3
    float4 xv[8];
#pragma unroll
    for (int it = 0; it < 8; it++) xv[it] = __ldcs(&xr[it * 32 + lane]);
    const unsigned char mk = (lane == 0) ? x_mask[b * LL + l] : 0;

    // 2) wait for k3 grid (acquire g_wy), then compute with coherent Wy loads
    GDC_WAIT();
    const float4* wyr = reinterpret_cast<const float4*>(&g_wy[b][0]);

    float acc = 0.0f;
#pragma unroll
    for (int it = 0; it < 8; it++) {
        const float4 wv = wyr[it * 32 + lane];   // plain LDG.E (coherent)
        acc = fmaf(xv[it].x, wv.x, acc);
        acc = fmaf(xv[it].y, wv.y, acc);
        acc = fmaf(xv[it].z, wv.z, acc);
        acc = fmaf(xv[it].w, wv.w, acc);
    }
#pragma unroll
    for (int o = 16; o; o >>= 1) acc += __shfl_xor_sync(0xffffffffu, acc, o);
    if (lane == 0)
        zrow[warp] = mk ? -INFINITY : acc;
    __syncthreads();

    // write z chunk directly to out + block partial (m, s)
    if (tid < RPB)
        out[b * LL + chunk * RPB + tid] = zrow[tid];
    if (warp == 0 && lane < RPB) {
        float m = zrow[lane];
        float s = 1.0f;
#pragma unroll
        for (int o = 4; o; o >>= 1) {
            float m2 = __shfl_xor_sync(0xffu, m, o);
            float s2 = __shfl_xor_sync(0xffu, s, o);
            lse_combine(m, s, m2, s2);
        }
        if (lane == 0) {
            g_pm[b][chunk] = m;
            g_ps[b][chunk] = s;
        }
    }
    __threadfence();
    __syncthreads();

    if (tid == 0) {
        const int old = atomicAdd(&g_cnt[b], 1);
        s_elect = (old == BPB - 1) ? 1.0f : 0.0f;
    }
    __syncthreads();
    if (s_elect == 0.0f) return;

    // ---- last block for batch b: finish log_softmax in-place ----
    __threadfence();                 // acquire all producers' writes
    if (tid == 0) g_cnt[b] = 0;      // reset for next graph replay

    if (warp == 0) {
        // combine BPB=128 partials: each lane owns 4
        float m = g_pm[b][lane];
        float s = g_ps[b][lane];
#pragma unroll
        for (int k = 1; k < 4; k++)
            lse_combine(m, s, g_pm[b][lane + 32 * k], g_ps[b][lane + 32 * k]);
#pragma unroll
        for (int o = 16; o; o >>= 1) {
            float m2 = __shfl_xor_sync(0xffffffffu, m, o);
            float s2 = __shfl_xor_sync(0xffffffffu, s, o);
            lse_combine(m, s, m2, s2);
        }
        if (lane == 0) s_lse = m + logf(s);
    }
    __syncthreads();
    const float lse = s_lse;

    float4* po = reinterpret_cast<float4*>(out + b * LL);
    for (int i = tid; i < LL / 4; i += 256) {
        float4 z = po[i];
        po[i] = make_float4(z.x - lse, z.y - lse, z.z - lse, z.w - lse);
    }
}

// ---------------------------------------------------------------------------
// Launch. Input order: x, y, x_mask, actions, weight, bias, wa_h
// PDL chain k1 -> k3 -> k4: prologues overlap upstream kernels.
// ---------------------------------------------------------------------------
extern "C" void kernel_launch(void* const* d_in, const int* in_sizes, int n_in,
                              void* d_out, int out_size)
{
    const float*         x       = (const float*)d_in[0];
    const float*         y_in    = (const float*)d_in[1];
    const unsigned char* x_mask  = (const unsigned char*)d_in[2];
    const int*           actions = (const int*)d_in[3];
    const float*         weight  = (const float*)d_in[4];
    const float*         bias    = (const float*)d_in[5];
    const float*         wa_h    = (const float*)d_in[6];
    float*               out     = (float*)d_out;

    k1_partial_gemm<<<dim3(XX / (128 * XC), YT, MSPLIT), 128>>>(wa_h, y_in, weight);

    cudaLaunchAttribute pdl[1];
    pdl[0].id = cudaLaunchAttributeProgrammaticStreamSerialization;
    pdl[0].val.programmaticStreamSerializationAllowed = 1;

    {
        cudaLaunchConfig_t cfg = {};
        cfg.gridDim  = dim3(BB);
        cfg.blockDim = dim3(1024);
        cfg.attrs    = pdl;
        cfg.numAttrs = 1;
        cudaLaunchKernelEx(&cfg, k3_softmax_wy, actions, bias);
    }
    {
        cudaLaunchConfig_t cfg = {};
        cfg.gridDim  = dim3(BB, BPB);
        cfg.blockDim = dim3(256);
        cfg.attrs    = pdl;
        cfg.numAttrs = 1;
        cudaLaunchKernelEx(&cfg, k4_fused, x, x_mask, out);
    }
}